// round 13
// baseline (speedup 1.0000x reference)
#include <cuda_runtime.h>
#include <cuda_fp16.h>
#include <math.h>
#include <stdint.h>

#define T_TOK 16384
#define DIM_H 4096
#define DIM_M 2048
#define NE    8

#define BM 128
#define BN 128
#define BK 32
#define STAGES 2
// stage layout: pitch 80B rows of 32 halfs (64B data + 16B pad)
//   Ah[128]  Al[128]  Bh[128]  Bl[128]
#define PITCH     80
#define A_LIMB_B  (128 * PITCH)               // 10240
#define B_BASE_B  (2 * A_LIMB_B)              // 20480
#define B_LIMB_B  (128 * PITCH)               // 10240
#define STAGE_B   (B_BASE_B + 2 * B_LIMB_B)   // 40960
#define SMEM_TOTAL (STAGES * STAGE_B)         // 81920  (x2 CTAs = 160KB/SM)

// ---------------- device scratch -------------------------------------------
__device__ __half g_Ah[(size_t)T_TOK * DIM_H];
__device__ __half g_Al[(size_t)T_TOK * DIM_H];
__device__ __half g_Bh[(size_t)DIM_M * DIM_H];
__device__ __half g_Bl[(size_t)DIM_M * DIM_H];
__device__ float  g_h1[(size_t)T_TOK * DIM_M];
__device__ float  g_usage[NE];
__device__ float  g_mass[NE];

// ---------------- PTX helpers (generic sm_80+ only) -------------------------
__device__ __forceinline__ uint32_t smem_u32(const void* p) {
    uint32_t a;
    asm("{ .reg .u64 t; cvta.to.shared.u64 t, %1; cvt.u32.u64 %0, t; }"
        : "=r"(a) : "l"(p));
    return a;
}
__device__ __forceinline__ void cp_async16(uint32_t s, const void* g) {
    asm volatile("cp.async.cg.shared.global [%0], [%1], 16;"
                 :: "r"(s), "l"(__cvta_generic_to_global(g)) : "memory");
}
__device__ __forceinline__ void cp_commit() {
    asm volatile("cp.async.commit_group;" ::: "memory");
}
template <int N> __device__ __forceinline__ void cp_wait() {
    asm volatile("cp.async.wait_group %0;" :: "n"(N) : "memory");
}
__device__ __forceinline__ void ldsm4(uint32_t* r, uint32_t a) {
    asm volatile("ldmatrix.sync.aligned.m8n8.x4.shared.b16 {%0,%1,%2,%3}, [%4];"
                 : "=r"(r[0]), "=r"(r[1]), "=r"(r[2]), "=r"(r[3]) : "r"(a));
}
__device__ __forceinline__ void mma16816(float* c, const uint32_t* a,
                                         uint32_t b0, uint32_t b1) {
    asm volatile(
        "mma.sync.aligned.m16n8k16.row.col.f32.f16.f16.f32 "
        "{%0,%1,%2,%3}, {%4,%5,%6,%7}, {%8,%9}, {%0,%1,%2,%3};"
        : "+f"(c[0]), "+f"(c[1]), "+f"(c[2]), "+f"(c[3])
        : "r"(a[0]), "r"(a[1]), "r"(a[2]), "r"(a[3]), "r"(b0), "r"(b1));
}

// ---------------- stats zero ------------------------------------------------
__global__ void zero_stats_kernel() {
    if (threadIdx.x < NE) { g_usage[threadIdx.x] = 0.f; g_mass[threadIdx.x] = 0.f; }
}

// ---------------- limb splits ----------------------------------------------
__global__ __launch_bounds__(256) void split_x_kernel(const float* __restrict__ x) {
    size_t i = ((size_t)blockIdx.x * 256 + threadIdx.x) * 8;
    float4 v0 = *(const float4*)(x + i);
    float4 v1 = *(const float4*)(x + i + 4);
    float f[8] = {v0.x, v0.y, v0.z, v0.w, v1.x, v1.y, v1.z, v1.w};
    __half h[8], l[8];
#pragma unroll
    for (int j = 0; j < 8; j++) {
        float s = f[j] * 64.f;
        h[j] = __float2half(s);
        l[j] = __float2half(s - __half2float(h[j]));
    }
    *(uint4*)(g_Ah + i) = *(uint4*)h;
    *(uint4*)(g_Al + i) = *(uint4*)l;
}

__global__ __launch_bounds__(1024) void split_w_kernel(const float* __restrict__ w1) {
    __shared__ float tile[32][33];
    int n0 = blockIdx.x * 32, k0 = blockIdx.y * 32;
    tile[threadIdx.y][threadIdx.x] =
        w1[(size_t)(k0 + threadIdx.y) * DIM_M + n0 + threadIdx.x];
    __syncthreads();
    int n = n0 + threadIdx.y, k = k0 + threadIdx.x;
    float s = tile[threadIdx.x][threadIdx.y] * 64.f;
    __half h = __float2half(s);
    __half l = __float2half(s - __half2float(h));
    g_Bh[(size_t)n * DIM_H + k] = h;
    g_Bl[(size_t)n * DIM_H + k] = l;
}

// ---------------- HMMA GEMM1: h1 = relu((x@w1)/4096 + b1) ------------------
// 2-limb fp16 split, 3 limb-products into f32 accum via mma.sync m16n8k16.
// 2 CTAs/SM (128 threads, 4 warps 2x2, warp tile 64x64), BK=32, 2 stages,
// wait<0> + single barrier per chunk. CTAs decorrelate barrier/load stalls.
__global__ __launch_bounds__(128, 2)
void gemm1_mma_kernel(const float* __restrict__ b1) {
    extern __shared__ __align__(128) char dsm[];
    const uint32_t sbase = smem_u32(dsm);

    const int tid   = threadIdx.x;
    const int lane  = tid & 31;
    const int warp  = tid >> 5;
    const int warpM = warp >> 1;      // 0..1
    const int warpN = warp & 1;       // 0..1
    const int bm = blockIdx.y * BM;
    const int bn = blockIdx.x * BN;

    // ---- stage loader (16 cp.async16 per thread) ----
    auto load_stage = [&](int chunk, int buf) {
        const int k0 = chunk * BK;
        const uint32_t sb = sbase + buf * STAGE_B;
#pragma unroll
        for (int j = 0; j < 8; j++) {            // A: 2 limbs x 128 rows x 4 segs
            int u = tid + j * 128;
            int limb = u >> 9, rem = u & 511, row = rem >> 2, seg = rem & 3;
            const __half* gp = (limb ? g_Al : g_Ah) +
                               (size_t)(bm + row) * DIM_H + k0 + seg * 8;
            cp_async16(sb + limb * A_LIMB_B + row * PITCH + seg * 16, gp);
        }
#pragma unroll
        for (int j = 0; j < 8; j++) {            // B: 2 limbs x 128 rows x 4 segs
            int u = tid + j * 128;
            int limb = u >> 9, rem = u & 511, row = rem >> 2, seg = rem & 3;
            const __half* gp = (limb ? g_Bl : g_Bh) +
                               (size_t)(bn + row) * DIM_H + k0 + seg * 8;
            cp_async16(sb + B_BASE_B + limb * B_LIMB_B + row * PITCH + seg * 16, gp);
        }
    };

    float acc[4][8][4];
#pragma unroll
    for (int i = 0; i < 4; i++)
#pragma unroll
        for (int n = 0; n < 8; n++)
#pragma unroll
            for (int v = 0; v < 4; v++) acc[i][n][v] = 0.f;

    const int CHUNKS = DIM_H / BK;    // 128

    load_stage(0, 0);
    cp_commit();

    // per-lane ldmatrix base offset within a 16-row x 32B tile block
    const uint32_t lmo = (uint32_t)((lane & 15) * PITCH + (lane >> 4) * 16);

    for (int i = 0; i < CHUNKS; i++) {
        cp_wait<0>();
        __syncthreads();

        // issue next stage's loads right after the barrier; overlaps compute(i)
        if (i + 1 < CHUNKS) {
            load_stage(i + 1, (i + 1) & 1);
            cp_commit();
        }

        const uint32_t sb = sbase + (i & 1) * STAGE_B;
        const uint32_t aBase = sb + (uint32_t)(warpM * 64) * PITCH + lmo;
        const uint32_t bBase = sb + B_BASE_B + (uint32_t)(warpN * 64) * PITCH + lmo;

#pragma unroll
        for (int ko = 0; ko < BK; ko += 16) {
            uint32_t aH[4][4], aL[4][4];
#pragma unroll
            for (int mi = 0; mi < 4; mi++) {
                ldsm4(aH[mi], aBase + mi * (16 * PITCH) + ko * 2);
                ldsm4(aL[mi], aBase + A_LIMB_B + mi * (16 * PITCH) + ko * 2);
            }
#pragma unroll
            for (int nt = 0; nt < 4; nt++) {
                uint32_t bH[4], bL[4];
                ldsm4(bH, bBase + nt * (16 * PITCH) + ko * 2);
                ldsm4(bL, bBase + B_LIMB_B + nt * (16 * PITCH) + ko * 2);
#pragma unroll
                for (int sub = 0; sub < 2; sub++) {
                    const int n = nt * 2 + sub;
                    const uint32_t bh0 = bH[sub], bh1 = bH[sub + 2];
                    const uint32_t bl0 = bL[sub], bl1 = bL[sub + 2];
#pragma unroll
                    for (int mi = 0; mi < 4; mi++) {
                        mma16816(acc[mi][n], aH[mi], bh0, bh1);
                        mma16816(acc[mi][n], aL[mi], bh0, bh1);
                        mma16816(acc[mi][n], aH[mi], bl0, bl1);
                    }
                }
            }
        }
    }

    // ---- epilogue: de-scale, +bias, relu, store ----
    const int rbase = bm + warpM * 64 + (lane >> 2);
    const int cbase = bn + warpN * 64 + (lane & 3) * 2;
    const float sc = 1.f / 4096.f;
#pragma unroll
    for (int mi = 0; mi < 4; mi++) {
#pragma unroll
        for (int n = 0; n < 8; n++) {
            const int col = cbase + n * 8;
            const float bb0 = b1[col], bb1 = b1[col + 1];
            const int r0 = rbase + mi * 16;
            float2 v0, v1;
            v0.x = fmaxf(acc[mi][n][0] * sc + bb0, 0.f);
            v0.y = fmaxf(acc[mi][n][1] * sc + bb1, 0.f);
            v1.x = fmaxf(acc[mi][n][2] * sc + bb0, 0.f);
            v1.y = fmaxf(acc[mi][n][3] * sc + bb1, 0.f);
            *(float2*)(g_h1 + (size_t)r0 * DIM_M + col) = v0;
            *(float2*)(g_h1 + (size_t)(r0 + 8) * DIM_M + col) = v1;
        }
    }
}

// ---------------- router ----------------------------------------------------
__global__ __launch_bounds__(256)
void router_kernel(const float* __restrict__ w2,
                   const float* __restrict__ b2,
                   float* __restrict__ out)
{
    __shared__ float sw2[NE][DIM_M];
    __shared__ float su[NE], sm[NE];
    const int tid = threadIdx.x;
    for (int i = tid; i < DIM_M * NE; i += 256) sw2[i & 7][i >> 3] = w2[i];
    if (tid < NE) { su[tid] = 0.f; sm[tid] = 0.f; }
    __syncthreads();

    const int wid = tid >> 5, lane = tid & 31;
    const int t = blockIdx.x * 8 + wid;
    const float* hrow = g_h1 + (size_t)t * DIM_M;

    float acc[NE];
#pragma unroll
    for (int e = 0; e < NE; e++) acc[e] = 0.f;
    for (int m = lane; m < DIM_M; m += 32) {
        float hv = hrow[m];
#pragma unroll
        for (int e = 0; e < NE; e++) acc[e] = fmaf(hv, sw2[e][m], acc[e]);
    }
#pragma unroll
    for (int e = 0; e < NE; e++)
#pragma unroll
        for (int o = 16; o > 0; o >>= 1)
            acc[e] += __shfl_down_sync(0xffffffffu, acc[e], o);

    if (lane == 0) {
        float l[NE], p[NE];
#pragma unroll
        for (int e = 0; e < NE; e++) l[e] = acc[e] + b2[e];
        float mx = l[0];
#pragma unroll
        for (int e = 1; e < NE; e++) mx = fmaxf(mx, l[e]);
        float s = 0.f;
#pragma unroll
        for (int e = 0; e < NE; e++) { p[e] = expf(l[e] - mx); s += p[e]; }
        float inv = 1.f / s;
#pragma unroll
        for (int e = 0; e < NE; e++) p[e] *= inv;

        int i1 = 0;
#pragma unroll
        for (int e = 1; e < NE; e++) if (p[e] > p[i1]) i1 = e;
        int i2 = (i1 == 0) ? 1 : 0;
#pragma unroll
        for (int e = 0; e < NE; e++) if (e != i1 && p[e] > p[i2]) i2 = e;

        float denom = fmaxf(p[i1] + p[i2], 1e-8f);
        float m1 = p[i1] / denom, m2 = p[i2] / denom;
        float* orow = out + (size_t)t * NE;
#pragma unroll
        for (int e = 0; e < NE; e++)
            orow[e] = (e == i1) ? m1 : ((e == i2) ? m2 : 0.f);
        atomicAdd(&su[i1], 1.f); atomicAdd(&su[i2], 1.f);
        atomicAdd(&sm[i1], m1);  atomicAdd(&sm[i2], m2);
    }
    __syncthreads();
    if (tid < NE) { atomicAdd(&g_usage[tid], su[tid]); atomicAdd(&g_mass[tid], sm[tid]); }
}

__global__ void aux_kernel(float* __restrict__ out, int out_size) {
    const float invT = 1.0f / (float)T_TOK;
    float a = 0.f;
#pragma unroll
    for (int e = 0; e < NE; e++) a += (g_usage[e] * invT) * (g_mass[e] * invT);
    a *= (float)NE;
    for (int i = T_TOK * NE; i < out_size; i++) out[i] = a;
}

// ---------------------------------------------------------------------------
extern "C" void kernel_launch(void* const* d_in, const int* in_sizes, int n_in,
                              void* d_out, int out_size)
{
    const float* x  = (const float*)d_in[0];
    const float* w1 = (const float*)d_in[1];
    const float* b1 = (const float*)d_in[2];
    const float* w2 = (const float*)d_in[3];
    const float* b2 = (const float*)d_in[4];
    float* out = (float*)d_out;

    cudaFuncSetAttribute(gemm1_mma_kernel,
                         cudaFuncAttributeMaxDynamicSharedMemorySize, SMEM_TOTAL);

    zero_stats_kernel<<<1, 32>>>();

    split_x_kernel<<<(int)(((size_t)T_TOK * DIM_H) / (256 * 8)), 256>>>(x);
    split_w_kernel<<<dim3(DIM_M / 32, DIM_H / 32), dim3(32, 32)>>>(w1);

    dim3 g1(DIM_M / BN, T_TOK / BM);   // (16, 128)
    gemm1_mma_kernel<<<g1, 128, SMEM_TOTAL>>>(b1);

    router_kernel<<<T_TOK / 8, 256>>>(w2, b2, out);

    aux_kernel<<<1, 1>>>(out, out_size);
}

// round 17
// speedup vs baseline: 1.1458x; 1.1458x over previous
#include <cuda_runtime.h>
#include <cuda_fp16.h>
#include <math.h>
#include <stdint.h>

#define T_TOK 16384
#define DIM_H 4096
#define DIM_M 2048
#define NE    8

#define BM 128
#define BN 256
#define BK 64
#define STAGES 2
// stage layout: pitch 144B rows of 64 halfs (128B data + 16B pad)
//   Ah[128]  Al[128]  Bh[256]  Bl[256]
#define PITCH     144
#define A_LIMB_B  (128 * PITCH)          // 18432
#define B_BASE_B  (2 * A_LIMB_B)         // 36864
#define B_LIMB_B  (256 * PITCH)          // 36864
#define STAGE_B   (B_BASE_B + 2 * B_LIMB_B)   // 110592
#define SMEM_TOTAL (STAGES * STAGE_B)         // 221184
#define HP 260                                 // h-tile smem pitch (floats)

// ---------------- device scratch -------------------------------------------
__device__ __half g_Ah[(size_t)T_TOK * DIM_H];
__device__ __half g_Al[(size_t)T_TOK * DIM_H];
__device__ __half g_Bh[(size_t)DIM_M * DIM_H];
__device__ __half g_Bl[(size_t)DIM_M * DIM_H];
__device__ float  g_plog[(size_t)8 * T_TOK * NE];   // partial logits per bn-slice
__device__ float  g_usage[NE];
__device__ float  g_mass[NE];

// ---------------- PTX helpers (generic sm_80+ only) -------------------------
__device__ __forceinline__ uint32_t smem_u32(const void* p) {
    uint32_t a;
    asm("{ .reg .u64 t; cvta.to.shared.u64 t, %1; cvt.u32.u64 %0, t; }"
        : "=r"(a) : "l"(p));
    return a;
}
__device__ __forceinline__ void cp_async16(uint32_t s, const void* g) {
    asm volatile("cp.async.cg.shared.global [%0], [%1], 16;"
                 :: "r"(s), "l"(__cvta_generic_to_global(g)) : "memory");
}
__device__ __forceinline__ void cp_commit() {
    asm volatile("cp.async.commit_group;" ::: "memory");
}
template <int N> __device__ __forceinline__ void cp_wait() {
    asm volatile("cp.async.wait_group %0;" :: "n"(N) : "memory");
}
__device__ __forceinline__ void ldsm4(uint32_t* r, uint32_t a) {
    asm volatile("ldmatrix.sync.aligned.m8n8.x4.shared.b16 {%0,%1,%2,%3}, [%4];"
                 : "=r"(r[0]), "=r"(r[1]), "=r"(r[2]), "=r"(r[3]) : "r"(a));
}
__device__ __forceinline__ void mma16816(float* c, const uint32_t* a,
                                         uint32_t b0, uint32_t b1) {
    asm volatile(
        "mma.sync.aligned.m16n8k16.row.col.f32.f16.f16.f32 "
        "{%0,%1,%2,%3}, {%4,%5,%6,%7}, {%8,%9}, {%0,%1,%2,%3};"
        : "+f"(c[0]), "+f"(c[1]), "+f"(c[2]), "+f"(c[3])
        : "r"(a[0]), "r"(a[1]), "r"(a[2]), "r"(a[3]), "r"(b0), "r"(b1));
}

// ---------------- stats zero ------------------------------------------------
__global__ void zero_stats_kernel() {
    if (threadIdx.x < NE) { g_usage[threadIdx.x] = 0.f; g_mass[threadIdx.x] = 0.f; }
}

// ---------------- limb splits ----------------------------------------------
__global__ __launch_bounds__(256) void split_x_kernel(const float* __restrict__ x) {
    size_t i = ((size_t)blockIdx.x * 256 + threadIdx.x) * 8;
    float4 v0 = *(const float4*)(x + i);
    float4 v1 = *(const float4*)(x + i + 4);
    float f[8] = {v0.x, v0.y, v0.z, v0.w, v1.x, v1.y, v1.z, v1.w};
    __half h[8], l[8];
#pragma unroll
    for (int j = 0; j < 8; j++) {
        float s = f[j] * 64.f;
        h[j] = __float2half(s);
        l[j] = __float2half(s - __half2float(h[j]));
    }
    *(uint4*)(g_Ah + i) = *(uint4*)h;
    *(uint4*)(g_Al + i) = *(uint4*)l;
}

__global__ __launch_bounds__(1024) void split_w_kernel(const float* __restrict__ w1) {
    __shared__ float tile[32][33];
    int n0 = blockIdx.x * 32, k0 = blockIdx.y * 32;
    tile[threadIdx.y][threadIdx.x] =
        w1[(size_t)(k0 + threadIdx.y) * DIM_M + n0 + threadIdx.x];
    __syncthreads();
    int n = n0 + threadIdx.y, k = k0 + threadIdx.x;
    float s = tile[threadIdx.x][threadIdx.y] * 64.f;
    __half h = __float2half(s);
    __half l = __float2half(s - __half2float(h));
    g_Bh[(size_t)n * DIM_H + k] = h;
    g_Bl[(size_t)n * DIM_H + k] = l;
}

// ---------------- HMMA GEMM1 + fused partial logits -------------------------
// 3-limb fp16 split (proven: rel_err 4.18e-6). R7 schedule: BK=64, 2 stages,
// wait<0>, 1 barrier per chunk. Epilogue: h tile -> smem, partial logits
// over this CTA's 256-dim slice -> g_plog[bx][token][e]. No g_h1 roundtrip.
__global__ __launch_bounds__(256, 1)
void gemm1_mma_kernel(const float* __restrict__ b1, const float* __restrict__ w2g) {
    extern __shared__ __align__(128) char dsm[];
    const uint32_t sbase = smem_u32(dsm);

    const int tid   = threadIdx.x;
    const int lane  = tid & 31;
    const int warp  = tid >> 5;
    const int warpM = warp >> 2;      // 0..1
    const int warpN = warp & 3;       // 0..3
    const int bm = blockIdx.y * BM;
    const int bn = blockIdx.x * BN;

    // ---- stage loader (24 cp.async16 per thread) ----
    auto load_stage = [&](int chunk, int buf) {
        const int k0 = chunk * BK;
        const uint32_t sb = sbase + buf * STAGE_B;
#pragma unroll
        for (int j = 0; j < 8; j++) {            // A: 2 limbs x 128 rows x 8 segs
            int u = tid + j * 256;
            int limb = u >> 10, rem = u & 1023, row = rem >> 3, seg = rem & 7;
            const __half* gp = (limb ? g_Al : g_Ah) +
                               (size_t)(bm + row) * DIM_H + k0 + seg * 8;
            cp_async16(sb + limb * A_LIMB_B + row * PITCH + seg * 16, gp);
        }
#pragma unroll
        for (int j = 0; j < 16; j++) {           // B: 2 limbs x 256 rows x 8 segs
            int u = tid + j * 256;
            int limb = u >> 11, rem = u & 2047, row = rem >> 3, seg = rem & 7;
            const __half* gp = (limb ? g_Bl : g_Bh) +
                               (size_t)(bn + row) * DIM_H + k0 + seg * 8;
            cp_async16(sb + B_BASE_B + limb * B_LIMB_B + row * PITCH + seg * 16, gp);
        }
    };

    float acc[4][8][4];
#pragma unroll
    for (int i = 0; i < 4; i++)
#pragma unroll
        for (int n = 0; n < 8; n++)
#pragma unroll
            for (int v = 0; v < 4; v++) acc[i][n][v] = 0.f;

    const int CHUNKS = DIM_H / BK;    // 64

    load_stage(0, 0);
    cp_commit();

    const uint32_t lmo = (uint32_t)((lane & 15) * PITCH + (lane >> 4) * 16);

    for (int i = 0; i < CHUNKS; i++) {
        cp_wait<0>();
        __syncthreads();

        if (i + 1 < CHUNKS) {
            load_stage(i + 1, (i + 1) & 1);
            cp_commit();
        }

        const uint32_t sb = sbase + (i & 1) * STAGE_B;
        const uint32_t aBase = sb + (uint32_t)(warpM * 64) * PITCH + lmo;
        const uint32_t bBase = sb + B_BASE_B + (uint32_t)(warpN * 64) * PITCH + lmo;

#pragma unroll
        for (int ko = 0; ko < BK; ko += 16) {
            uint32_t aH[4][4], aL[4][4];
#pragma unroll
            for (int mi = 0; mi < 4; mi++) {
                ldsm4(aH[mi], aBase + mi * (16 * PITCH) + ko * 2);
                ldsm4(aL[mi], aBase + A_LIMB_B + mi * (16 * PITCH) + ko * 2);
            }
#pragma unroll
            for (int nt = 0; nt < 4; nt++) {
                uint32_t bH[4], bL[4];
                ldsm4(bH, bBase + nt * (16 * PITCH) + ko * 2);
                ldsm4(bL, bBase + B_LIMB_B + nt * (16 * PITCH) + ko * 2);
#pragma unroll
                for (int sub = 0; sub < 2; sub++) {
                    const int n = nt * 2 + sub;
                    const uint32_t bh0 = bH[sub], bh1 = bH[sub + 2];
                    const uint32_t bl0 = bL[sub], bl1 = bL[sub + 2];
#pragma unroll
                    for (int mi = 0; mi < 4; mi++) {
                        mma16816(acc[mi][n], aH[mi], bh0, bh1);
                        mma16816(acc[mi][n], aL[mi], bh0, bh1);
                        mma16816(acc[mi][n], aH[mi], bl0, bl1);
                    }
                }
            }
        }
    }

    // ---- epilogue: de-scale, +bias, relu -> smem h tile (fp32) ----
    __syncthreads();                  // all reads of stage buffers done
    float* sh = (float*)dsm;          // 128 x HP floats = 133120 B <= 221184
    {
        const int rloc = warpM * 64 + (lane >> 2);
        const int cloc = warpN * 64 + (lane & 3) * 2;
        const float sc = 1.f / 4096.f;
#pragma unroll
        for (int mi = 0; mi < 4; mi++) {
#pragma unroll
            for (int n = 0; n < 8; n++) {
                const int c = cloc + n * 8;
                const float bb0 = b1[bn + c], bb1 = b1[bn + c + 1];
                const int r0 = rloc + mi * 16;
                sh[r0 * HP + c]           = fmaxf(acc[mi][n][0] * sc + bb0, 0.f);
                sh[r0 * HP + c + 1]       = fmaxf(acc[mi][n][1] * sc + bb1, 0.f);
                sh[(r0 + 8) * HP + c]     = fmaxf(acc[mi][n][2] * sc + bb0, 0.f);
                sh[(r0 + 8) * HP + c + 1] = fmaxf(acc[mi][n][3] * sc + bb1, 0.f);
            }
        }
    }

    // per-lane w2 rows (dims lane+32k of this CTA's slice), coalesced L2-hot
    float w2r[8][8];
#pragma unroll
    for (int k = 0; k < 8; k++) {
        const float4* wp = (const float4*)(w2g + (size_t)(bn + lane + 32 * k) * NE);
        float4 a = wp[0], b = wp[1];
        w2r[k][0] = a.x; w2r[k][1] = a.y; w2r[k][2] = a.z; w2r[k][3] = a.w;
        w2r[k][4] = b.x; w2r[k][5] = b.y; w2r[k][6] = b.z; w2r[k][7] = b.w;
    }
    __syncthreads();

    // ---- fused partial logits: warp w handles tokens w*16..w*16+15 ----
#pragma unroll 1
    for (int tt = 0; tt < 16; tt++) {
        const int t = warp * 16 + tt;
        float p[NE];
#pragma unroll
        for (int e = 0; e < NE; e++) p[e] = 0.f;
#pragma unroll
        for (int k = 0; k < 8; k++) {
            const float hv = sh[t * HP + lane + 32 * k];
#pragma unroll
            for (int e = 0; e < NE; e++) p[e] = fmaf(hv, w2r[k][e], p[e]);
        }
#pragma unroll
        for (int e = 0; e < NE; e++)
#pragma unroll
            for (int o = 16; o > 0; o >>= 1)
                p[e] += __shfl_xor_sync(0xffffffffu, p[e], o);
        if (lane == 0) {
            float4* dst = (float4*)(g_plog +
                ((size_t)blockIdx.x * T_TOK + bm + t) * NE);
            dst[0] = make_float4(p[0], p[1], p[2], p[3]);
            dst[1] = make_float4(p[4], p[5], p[6], p[7]);
        }
    }
}

// ---------------- finalize: sum partials, softmax, top-2, stats -------------
__global__ __launch_bounds__(256)
void finalize_kernel(const float* __restrict__ b2, float* __restrict__ out) {
    __shared__ float su[NE], sm[NE];
    const int tid = threadIdx.x;
    if (tid < NE) { su[tid] = 0.f; sm[tid] = 0.f; }
    __syncthreads();

    const int t = blockIdx.x * 256 + tid;
    float l[NE];
#pragma unroll
    for (int e = 0; e < NE; e++) l[e] = b2[e];
#pragma unroll
    for (int s = 0; s < 8; s++) {
        const float4* pp = (const float4*)(g_plog + ((size_t)s * T_TOK + t) * NE);
        float4 a = pp[0], b = pp[1];
        l[0] += a.x; l[1] += a.y; l[2] += a.z; l[3] += a.w;
        l[4] += b.x; l[5] += b.y; l[6] += b.z; l[7] += b.w;
    }

    float p[NE];
    float mx = l[0];
#pragma unroll
    for (int e = 1; e < NE; e++) mx = fmaxf(mx, l[e]);
    float s = 0.f;
#pragma unroll
    for (int e = 0; e < NE; e++) { p[e] = expf(l[e] - mx); s += p[e]; }
    float inv = 1.f / s;
#pragma unroll
    for (int e = 0; e < NE; e++) p[e] *= inv;

    int i1 = 0;
#pragma unroll
    for (int e = 1; e < NE; e++) if (p[e] > p[i1]) i1 = e;
    int i2 = (i1 == 0) ? 1 : 0;
#pragma unroll
    for (int e = 0; e < NE; e++) if (e != i1 && p[e] > p[i2]) i2 = e;

    float denom = fmaxf(p[i1] + p[i2], 1e-8f);
    float m1 = p[i1] / denom, m2 = p[i2] / denom;
    float* orow = out + (size_t)t * NE;
#pragma unroll
    for (int e = 0; e < NE; e++)
        orow[e] = (e == i1) ? m1 : ((e == i2) ? m2 : 0.f);
    atomicAdd(&su[i1], 1.f); atomicAdd(&su[i2], 1.f);
    atomicAdd(&sm[i1], m1);  atomicAdd(&sm[i2], m2);

    __syncthreads();
    if (tid < NE) { atomicAdd(&g_usage[tid], su[tid]); atomicAdd(&g_mass[tid], sm[tid]); }
}

__global__ void aux_kernel(float* __restrict__ out, int out_size) {
    const float invT = 1.0f / (float)T_TOK;
    float a = 0.f;
#pragma unroll
    for (int e = 0; e < NE; e++) a += (g_usage[e] * invT) * (g_mass[e] * invT);
    a *= (float)NE;
    for (int i = T_TOK * NE; i < out_size; i++) out[i] = a;
}

// ---------------------------------------------------------------------------
extern "C" void kernel_launch(void* const* d_in, const int* in_sizes, int n_in,
                              void* d_out, int out_size)
{
    const float* x  = (const float*)d_in[0];
    const float* w1 = (const float*)d_in[1];
    const float* b1 = (const float*)d_in[2];
    const float* w2 = (const float*)d_in[3];
    const float* b2 = (const float*)d_in[4];
    float* out = (float*)d_out;

    cudaFuncSetAttribute(gemm1_mma_kernel,
                         cudaFuncAttributeMaxDynamicSharedMemorySize, SMEM_TOTAL);

    zero_stats_kernel<<<1, 32>>>();

    split_x_kernel<<<(int)(((size_t)T_TOK * DIM_H) / (256 * 8)), 256>>>(x);
    split_w_kernel<<<dim3(DIM_M / 32, DIM_H / 32), dim3(32, 32)>>>(w1);

    dim3 g1(DIM_M / BN, T_TOK / BM);   // (8, 128)
    gemm1_mma_kernel<<<g1, 256, SMEM_TOTAL>>>(b1, w2);

    finalize_kernel<<<T_TOK / 256, 256>>>(b2, out);

    aux_kernel<<<1, 1>>>(out, out_size);
}